// round 3
// baseline (speedup 1.0000x reference)
#include <cuda_runtime.h>
#include <cuda_bf16.h>

// Problem constants
#define BATCH   16
#define HDIM    224
#define WDIM    224
#define CDIM    64
#define HO      112
#define WO      112
#define NPATCH  (HO * WO)            // 12544 per image
#define TOPK    1254

// float4-unit strides for x [B,H,W,C] NHWC
#define IMG4    (HDIM * WDIM * (CDIM / 4))   // 802816
#define ROW4    (WDIM * (CDIM / 4))          // 3584
#define PIX4    (CDIM / 4)                   // 16

// Scratch (no cudaMalloc allowed)
__device__ float    d_g[BATCH * NPATCH];
__device__ unsigned d_thr[BATCH];
__device__ int      d_ties[BATCH];
__device__ int      d_ctr[BATCH];

// Order-preserving float->uint transform (ascending uint == ascending float)
__device__ __forceinline__ unsigned f2o(float f) {
    unsigned u = __float_as_uint(f);
    return (u & 0x80000000u) ? ~u : (u | 0x80000000u);
}

// ---------------------------------------------------------------------------
// Kernel 1: gating conv (2x2, stride 2, 1 out-channel). One warp per patch.
// Patch = 2 rows x 2 pixels x 64 ch = 64 float4. Lane l handles float4 p=l
// (row kh=0) and p=l+32 (row kh=1). Weight layout [kh,kw,c] matches p order.
// ---------------------------------------------------------------------------
__global__ void __launch_bounds__(256) conv_gate_k(
        const float* __restrict__ x, const float* __restrict__ wk) {
    int warp = (blockIdx.x * blockDim.x + threadIdx.x) >> 5;
    int lane = threadIdx.x & 31;
    if (warp >= BATCH * NPATCH) return;

    int b  = warp / NPATCH;
    int r  = warp - b * NPATCH;
    int ho = r / WO;
    int wo = r - ho * WO;

    const float4* x4 = (const float4*)x;
    const float4* w4 = (const float4*)wk;

    int base = b * IMG4 + (2 * ho) * ROW4 + (2 * wo) * PIX4;
    int kw = lane >> 4;           // 0 or 1
    int c4 = lane & 15;           // 0..15
    int off = kw * PIX4 + c4;

    float4 xa = __ldg(&x4[base + off]);
    float4 xb = __ldg(&x4[base + ROW4 + off]);
    float4 wa = __ldg(&w4[lane]);
    float4 wb = __ldg(&w4[lane + 32]);

    float s = xa.x * wa.x + xa.y * wa.y + xa.z * wa.z + xa.w * wa.w
            + xb.x * wb.x + xb.y * wb.y + xb.z * wb.z + xb.w * wb.w;
    #pragma unroll
    for (int o = 16; o; o >>= 1) s += __shfl_xor_sync(0xffffffffu, s, o);
    if (lane == 0) d_g[warp] = s;
}

// ---------------------------------------------------------------------------
// Kernel 2: per-image radix select for the K-th largest score.
// One block per image. 4 MSB-first byte passes; at the end, s_prefix is the
// exact bit pattern of the K-th largest (transformed) value and s_rem is how
// many tie-valued elements may be kept.
// ---------------------------------------------------------------------------
__global__ void __launch_bounds__(512) select_k(void) {
    int b = blockIdx.x;
    const float* g = d_g + b * NPATCH;

    __shared__ unsigned hist[256];
    __shared__ unsigned s_prefix;
    __shared__ int      s_rem;

    if (threadIdx.x == 0) { s_prefix = 0; s_rem = TOPK; d_ctr[b] = 0; }

    for (int shift = 24; shift >= 0; shift -= 8) {
        for (int i = threadIdx.x; i < 256; i += blockDim.x) hist[i] = 0;
        __syncthreads();

        unsigned prefix = s_prefix;
        unsigned hm = (shift == 24) ? 0u : ~((1u << (shift + 8)) - 1u);
        for (int i = threadIdx.x; i < NPATCH; i += blockDim.x) {
            unsigned u = f2o(g[i]);
            if ((u & hm) == prefix)
                atomicAdd(&hist[(u >> shift) & 255u], 1u);
        }
        __syncthreads();

        if (threadIdx.x == 0) {
            int rem = s_rem;
            int d = 255;
            for (; d > 0; --d) {
                if (rem > (int)hist[d]) rem -= (int)hist[d];
                else break;
            }
            s_rem = rem;
            s_prefix = prefix | ((unsigned)d << shift);
        }
        __syncthreads();
    }
    if (threadIdx.x == 0) { d_thr[b] = s_prefix; d_ties[b] = s_rem; }
}

// ---------------------------------------------------------------------------
// Kernel 3: threshold the scores in place -> dense gate (exactly K nonzeros).
// ---------------------------------------------------------------------------
__global__ void __launch_bounds__(256) gate_pass_k(void) {
    int i = blockIdx.x * blockDim.x + threadIdx.x;
    if (i >= BATCH * NPATCH) return;
    int b = i / NPATCH;
    float v = d_g[i];
    unsigned u = f2o(v);
    unsigned t = d_thr[b];
    float out;
    if (u > t) out = v;
    else if (u == t) {
        int p = atomicAdd(&d_ctr[b], 1);
        out = (p < d_ties[b]) ? v : 0.0f;
    } else out = 0.0f;
    d_g[i] = out;
}

// ---------------------------------------------------------------------------
// Kernel 4: out = x * gate_full. Flat float4 kernel; 32 consecutive float4
// indices cover exactly one (2-pixel) gate cell, so gate is warp-uniform and
// zero-gate warps skip the x read entirely (write zeros only).
// ---------------------------------------------------------------------------
__global__ void __launch_bounds__(256) apply_gate_k(
        const float* __restrict__ x, float* __restrict__ out) {
    int i = blockIdx.x * blockDim.x + threadIdx.x;   // float4 index
    int b = i / IMG4;
    int r = i - b * IMG4;
    int h = r / ROW4;
    int w = (r - h * ROW4) >> 4;     // pixel index / PIX4

    float gv = d_g[b * NPATCH + (h >> 1) * WO + (w >> 1)];

    float4 o;
    if (gv != 0.0f) {
        float4 v = ((const float4*)x)[i];
        o = make_float4(v.x * gv, v.y * gv, v.z * gv, v.w * gv);
    } else {
        o = make_float4(0.f, 0.f, 0.f, 0.f);
    }
    ((float4*)out)[i] = o;
}

// ---------------------------------------------------------------------------
extern "C" void kernel_launch(void* const* d_in, const int* in_sizes, int n_in,
                              void* d_out, int out_size) {
    const float* x  = (const float*)d_in[0];
    const float* wk = (const float*)d_in[1];
    float* out = (float*)d_out;

    // 1) conv: one warp per patch, 8 warps/block
    int npatch_total = BATCH * NPATCH;               // 200704
    conv_gate_k<<<npatch_total / 8, 256>>>(x, wk);

    // 2) radix select, one block per image
    select_k<<<BATCH, 512>>>();

    // 3) gate threshold pass
    gate_pass_k<<<(npatch_total + 255) / 256, 256>>>();

    // 4) apply gate
    int n4 = out_size / 4;                           // 12,845,056
    apply_gate_k<<<n4 / 256, 256>>>(x, out);
}